// round 1
// baseline (speedup 1.0000x reference)
#include <cuda_runtime.h>

// Problem constants
#define T_   1024
#define B_   8
#define E_   512
#define H_   8
#define D_   64
#define BH_  (B_ * H_)          // 64
#define M_   (T_ * B_)          // 8192 rows for the two linear layers
#define K3E  (3 * E_)           // 1536
#define SCALE_ 0.125f           // D^-0.5 = 64^-0.5

#define TT_  (T_ * T_)                       // 1048576
#define OUT_OFF2 (2 * (size_t)T_ * B_ * E_)  // 8388608 floats (start of aw_avg block)
#define BTT_ ((size_t)B_ * T_ * T_)          // 8388608

// -------------------- scratch (device globals; no runtime allocation) ------
__device__ float g_qkv_r[(size_t)M_ * K3E];   // 50.3 MB
__device__ float g_qkv_i[(size_t)M_ * K3E];
__device__ float g_aw_r[(size_t)BH_ * TT_];   // 268 MB (scores, then softmaxed in place)
__device__ float g_aw_i[(size_t)BH_ * TT_];
__device__ float g_attn_r[(size_t)M_ * E_];   // 16.8 MB, stored directly in [T,B,E] layout
__device__ float g_attn_i[(size_t)M_ * E_];

// ---------------------------------------------------------------------------
// Generic complex GEMM: C = (Ar + iAi) @ (Br + iBi)^T + bias
//   A: [M, K] row-major, B: [N, K] row-major, C: [M, N]
//   M given by gridDim.y*64, tiles 64x64, 256 threads, 4x4 per thread (x2 complex)
// ---------------------------------------------------------------------------
__global__ __launch_bounds__(256) void cgemm64(
    const float* __restrict__ Ar, const float* __restrict__ Ai,
    const float* __restrict__ Br, const float* __restrict__ Bi,
    const float* __restrict__ biasr, const float* __restrict__ biasi,
    float* __restrict__ Cr, float* __restrict__ Ci,
    int N, int K)
{
    __shared__ float Asr[16][68], Asi[16][68], Bsr[16][68], Bsi[16][68];

    const int tid = threadIdx.x;
    const int m0 = blockIdx.y << 6;
    const int n0 = blockIdx.x << 6;
    const int tx = tid & 15;          // n direction
    const int ty = tid >> 4;          // m direction
    const int lr = tid >> 2;          // loader row (0..63)
    const int lk = (tid & 3) << 2;    // loader k offset (0,4,8,12)

    const float* Arp = Ar + (size_t)(m0 + lr) * K + lk;
    const float* Aip = Ai + (size_t)(m0 + lr) * K + lk;
    const float* Brp = Br + (size_t)(n0 + lr) * K + lk;
    const float* Bip = Bi + (size_t)(n0 + lr) * K + lk;

    float cr[4][4] = {{0.f}}, ci[4][4] = {{0.f}};

    for (int k0 = 0; k0 < K; k0 += 16) {
        float4 a4r = *(const float4*)(Arp + k0);
        float4 a4i = *(const float4*)(Aip + k0);
        float4 b4r = *(const float4*)(Brp + k0);
        float4 b4i = *(const float4*)(Bip + k0);
        __syncthreads();
        Asr[lk+0][lr] = a4r.x; Asr[lk+1][lr] = a4r.y; Asr[lk+2][lr] = a4r.z; Asr[lk+3][lr] = a4r.w;
        Asi[lk+0][lr] = a4i.x; Asi[lk+1][lr] = a4i.y; Asi[lk+2][lr] = a4i.z; Asi[lk+3][lr] = a4i.w;
        Bsr[lk+0][lr] = b4r.x; Bsr[lk+1][lr] = b4r.y; Bsr[lk+2][lr] = b4r.z; Bsr[lk+3][lr] = b4r.w;
        Bsi[lk+0][lr] = b4i.x; Bsi[lk+1][lr] = b4i.y; Bsi[lk+2][lr] = b4i.z; Bsi[lk+3][lr] = b4i.w;
        __syncthreads();
#pragma unroll
        for (int kk = 0; kk < 16; kk++) {
            float4 v;
            v = *(const float4*)&Asr[kk][ty << 2];
            float arv[4] = {v.x, v.y, v.z, v.w};
            v = *(const float4*)&Asi[kk][ty << 2];
            float aiv[4] = {v.x, v.y, v.z, v.w};
            v = *(const float4*)&Bsr[kk][tx << 2];
            float brv[4] = {v.x, v.y, v.z, v.w};
            v = *(const float4*)&Bsi[kk][tx << 2];
            float biv[4] = {v.x, v.y, v.z, v.w};
#pragma unroll
            for (int i = 0; i < 4; i++)
#pragma unroll
                for (int j = 0; j < 4; j++) {
                    cr[i][j] += arv[i] * brv[j] - aiv[i] * biv[j];
                    ci[i][j] += aiv[i] * brv[j] + arv[i] * biv[j];
                }
        }
    }

#pragma unroll
    for (int i = 0; i < 4; i++) {
        int m = m0 + (ty << 2) + i;
#pragma unroll
        for (int j = 0; j < 4; j++) {
            int n = n0 + (tx << 2) + j;
            Cr[(size_t)m * N + n] = cr[i][j] + biasr[n];
            Ci[(size_t)m * N + n] = ci[i][j] + biasi[n];
        }
    }
}

// ---------------------------------------------------------------------------
// Scores: s_r = (q_r.k_r + q_i.k_i)*SCALE ; s_i = (q_i.k_r - q_r.k_i)*SCALE
// q/k slices read directly from g_qkv with head indexing.
// Grid: (s_tiles=16, t_tiles=16, bh=64). Block 256, 64x64 tile, K=64.
// ---------------------------------------------------------------------------
__global__ __launch_bounds__(256) void score_kernel()
{
    __shared__ float Qr[16][68], Qi[16][68], Kr[16][68], Ki[16][68];

    const int bh = blockIdx.z;
    const int b = bh >> 3, h = bh & 7;
    const int t0 = blockIdx.y << 6;
    const int s0 = blockIdx.x << 6;

    const int tid = threadIdx.x;
    const int tx = tid & 15, ty = tid >> 4;
    const int lr = tid >> 2, lk = (tid & 3) << 2;

    const size_t qoff = ((size_t)(t0 + lr) * B_ + b) * K3E + h * D_ + lk;
    const size_t koff = ((size_t)(s0 + lr) * B_ + b) * K3E + E_ + h * D_ + lk;

    float cr[4][4] = {{0.f}}, ci[4][4] = {{0.f}};

    for (int k0 = 0; k0 < D_; k0 += 16) {
        float4 q4r = *(const float4*)&g_qkv_r[qoff + k0];
        float4 q4i = *(const float4*)&g_qkv_i[qoff + k0];
        float4 k4r = *(const float4*)&g_qkv_r[koff + k0];
        float4 k4i = *(const float4*)&g_qkv_i[koff + k0];
        __syncthreads();
        Qr[lk+0][lr] = q4r.x; Qr[lk+1][lr] = q4r.y; Qr[lk+2][lr] = q4r.z; Qr[lk+3][lr] = q4r.w;
        Qi[lk+0][lr] = q4i.x; Qi[lk+1][lr] = q4i.y; Qi[lk+2][lr] = q4i.z; Qi[lk+3][lr] = q4i.w;
        Kr[lk+0][lr] = k4r.x; Kr[lk+1][lr] = k4r.y; Kr[lk+2][lr] = k4r.z; Kr[lk+3][lr] = k4r.w;
        Ki[lk+0][lr] = k4i.x; Ki[lk+1][lr] = k4i.y; Ki[lk+2][lr] = k4i.z; Ki[lk+3][lr] = k4i.w;
        __syncthreads();
#pragma unroll
        for (int kk = 0; kk < 16; kk++) {
            float4 v;
            v = *(const float4*)&Qr[kk][ty << 2];
            float qrv[4] = {v.x, v.y, v.z, v.w};
            v = *(const float4*)&Qi[kk][ty << 2];
            float qiv[4] = {v.x, v.y, v.z, v.w};
            v = *(const float4*)&Kr[kk][tx << 2];
            float krv[4] = {v.x, v.y, v.z, v.w};
            v = *(const float4*)&Ki[kk][tx << 2];
            float kiv[4] = {v.x, v.y, v.z, v.w};
#pragma unroll
            for (int i = 0; i < 4; i++)
#pragma unroll
                for (int j = 0; j < 4; j++) {
                    cr[i][j] += qrv[i] * krv[j] + qiv[i] * kiv[j];
                    ci[i][j] += qiv[i] * krv[j] - qrv[i] * kiv[j];
                }
        }
    }

    const size_t base = (size_t)bh * TT_;
#pragma unroll
    for (int i = 0; i < 4; i++) {
        int t = t0 + (ty << 2) + i;
#pragma unroll
        for (int j = 0; j < 4; j++) {
            int s = s0 + (tx << 2) + j;
            g_aw_r[base + (size_t)t * T_ + s] = cr[i][j] * SCALE_;
            g_aw_i[base + (size_t)t * T_ + s] = ci[i][j] * SCALE_;
        }
    }
}

// ---------------------------------------------------------------------------
// Row softmax in place over g_aw_r / g_aw_i. One block per row.
// blockIdx.x in [0, 2*BH*T): first half = real, second = imag.
// ---------------------------------------------------------------------------
__global__ __launch_bounds__(256) void softmax_kernel()
{
    const unsigned rows = BH_ * T_;            // 65536
    const unsigned x = blockIdx.x;
    float* buf = (x >= rows) ? g_aw_i : g_aw_r;
    const size_t row = (size_t)(x & (rows - 1));
    float* p = buf + row * T_;

    const int tid = threadIdx.x;
    float4 v = *(const float4*)&p[tid << 2];

    __shared__ float red[256];
    float m = fmaxf(fmaxf(v.x, v.y), fmaxf(v.z, v.w));
    red[tid] = m;
    __syncthreads();
#pragma unroll
    for (int off = 128; off > 0; off >>= 1) {
        if (tid < off) red[tid] = fmaxf(red[tid], red[tid + off]);
        __syncthreads();
    }
    const float rmax = red[0];
    __syncthreads();

    float4 e;
    e.x = expf(v.x - rmax);
    e.y = expf(v.y - rmax);
    e.z = expf(v.z - rmax);
    e.w = expf(v.w - rmax);
    red[tid] = e.x + e.y + e.z + e.w;
    __syncthreads();
#pragma unroll
    for (int off = 128; off > 0; off >>= 1) {
        if (tid < off) red[tid] += red[tid + off];
        __syncthreads();
    }
    const float inv = 1.0f / red[0];

    e.x *= inv; e.y *= inv; e.z *= inv; e.w *= inv;
    *(float4*)&p[tid << 2] = e;
}

// ---------------------------------------------------------------------------
// Head-average of attention weights -> d_out second block [2, B, T, T]
// grid (t=1024, b=8), 256 threads * 4 s each.
// ---------------------------------------------------------------------------
__global__ __launch_bounds__(256) void avg_kernel(float* __restrict__ out)
{
    const int t = blockIdx.x;
    const int b = blockIdx.y;
    const int s = threadIdx.x << 2;

    float4 sr = {0.f, 0.f, 0.f, 0.f};
    float4 si = {0.f, 0.f, 0.f, 0.f};
#pragma unroll
    for (int h = 0; h < H_; h++) {
        size_t base = ((size_t)(b * H_ + h) * T_ + t) * T_ + s;
        float4 r = *(const float4*)&g_aw_r[base];
        float4 im = *(const float4*)&g_aw_i[base];
        sr.x += r.x;  sr.y += r.y;  sr.z += r.z;  sr.w += r.w;
        si.x += im.x; si.y += im.y; si.z += im.z; si.w += im.w;
    }
    const float inv = 1.0f / (float)H_;
    sr.x *= inv; sr.y *= inv; sr.z *= inv; sr.w *= inv;
    si.x *= inv; si.y *= inv; si.z *= inv; si.w *= inv;

    size_t o = ((size_t)b * T_ + t) * T_ + s;
    *(float4*)&out[OUT_OFF2 + o]        = sr;
    *(float4*)&out[OUT_OFF2 + BTT_ + o] = si;
}

// ---------------------------------------------------------------------------
// PV: attn_r = aw_r@v_r + aw_i@v_i ; attn_i = aw_i@v_r - aw_r@v_i
// Grid: (t_tiles=16, bh=64). Output written directly in [T, B, E] layout.
// ---------------------------------------------------------------------------
__global__ __launch_bounds__(256) void pv_kernel()
{
    __shared__ float Awr[16][68], Awi[16][68], Vr[16][68], Vi[16][68];

    const int bh = blockIdx.y;
    const int b = bh >> 3, h = bh & 7;
    const int t0 = blockIdx.x << 6;

    const int tid = threadIdx.x;
    const int tx = tid & 15, ty = tid >> 4;
    // aw loader: 64 t-rows x 16 s-cols (transposed into smem)
    const int alr = tid >> 2, alk = (tid & 3) << 2;
    // v loader: 16 s-rows x 64 d-cols (direct)
    const int vls = tid >> 4, vld = (tid & 15) << 2;

    float cr[4][4] = {{0.f}}, ci[4][4] = {{0.f}};

    const size_t awbase = (size_t)bh * TT_ + (size_t)(t0 + alr) * T_ + alk;

    for (int s0 = 0; s0 < T_; s0 += 16) {
        float4 a4r = *(const float4*)&g_aw_r[awbase + s0];
        float4 a4i = *(const float4*)&g_aw_i[awbase + s0];
        size_t voff = ((size_t)(s0 + vls) * B_ + b) * K3E + 2 * E_ + h * D_ + vld;
        float4 v4r = *(const float4*)&g_qkv_r[voff];
        float4 v4i = *(const float4*)&g_qkv_i[voff];
        __syncthreads();
        Awr[alk+0][alr] = a4r.x; Awr[alk+1][alr] = a4r.y; Awr[alk+2][alr] = a4r.z; Awr[alk+3][alr] = a4r.w;
        Awi[alk+0][alr] = a4i.x; Awi[alk+1][alr] = a4i.y; Awi[alk+2][alr] = a4i.z; Awi[alk+3][alr] = a4i.w;
        *(float4*)&Vr[vls][vld] = v4r;
        *(float4*)&Vi[vls][vld] = v4i;
        __syncthreads();
#pragma unroll
        for (int kk = 0; kk < 16; kk++) {
            float4 v;
            v = *(const float4*)&Awr[kk][ty << 2];
            float arv[4] = {v.x, v.y, v.z, v.w};
            v = *(const float4*)&Awi[kk][ty << 2];
            float aiv[4] = {v.x, v.y, v.z, v.w};
            v = *(const float4*)&Vr[kk][tx << 2];
            float vrv[4] = {v.x, v.y, v.z, v.w};
            v = *(const float4*)&Vi[kk][tx << 2];
            float viv[4] = {v.x, v.y, v.z, v.w};
#pragma unroll
            for (int i = 0; i < 4; i++)
#pragma unroll
                for (int j = 0; j < 4; j++) {
                    cr[i][j] += arv[i] * vrv[j] + aiv[i] * viv[j];
                    ci[i][j] += aiv[i] * vrv[j] - arv[i] * viv[j];
                }
        }
    }

#pragma unroll
    for (int i = 0; i < 4; i++) {
        int t = t0 + (ty << 2) + i;
#pragma unroll
        for (int j = 0; j < 4; j++) {
            int d = (tx << 2) + j;
            size_t o = ((size_t)t * B_ + b) * E_ + h * D_ + d;
            g_attn_r[o] = cr[i][j];
            g_attn_i[o] = ci[i][j];
        }
    }
}

// ---------------------------------------------------------------------------
extern "C" void kernel_launch(void* const* d_in, const int* in_sizes, int n_in,
                              void* d_out, int out_size)
{
    const float* query_r = (const float*)d_in[0];
    const float* query_i = (const float*)d_in[1];
    const float* W_qkv_r = (const float*)d_in[2];
    const float* W_qkv_i = (const float*)d_in[3];
    const float* b_qkv_r = (const float*)d_in[4];
    const float* b_qkv_i = (const float*)d_in[5];
    const float* W_out_r = (const float*)d_in[6];
    const float* W_out_i = (const float*)d_in[7];
    const float* b_out_r = (const float*)d_in[8];
    const float* b_out_i = (const float*)d_in[9];
    float* out = (float*)d_out;

    float *gqkvr, *gqkvi, *gatr, *gati;
    cudaGetSymbolAddress((void**)&gqkvr, g_qkv_r);
    cudaGetSymbolAddress((void**)&gqkvi, g_qkv_i);
    cudaGetSymbolAddress((void**)&gatr, g_attn_r);
    cudaGetSymbolAddress((void**)&gati, g_attn_i);

    dim3 blk(256);

    // 1) QKV complex linear: [8192,512] x [1536,512]^T -> [8192,1536]
    cgemm64<<<dim3(K3E / 64, M_ / 64), blk>>>(
        query_r, query_i, W_qkv_r, W_qkv_i, b_qkv_r, b_qkv_i,
        gqkvr, gqkvi, K3E, E_);

    // 2) Attention scores (pre-softmax, scaled)
    score_kernel<<<dim3(T_ / 64, T_ / 64, BH_), blk>>>();

    // 3) Softmax in place (real + imag rows)
    softmax_kernel<<<dim3(2 * BH_ * T_), blk>>>();

    // 4) Head-averaged attention weights -> d_out tail
    avg_kernel<<<dim3(T_, B_), blk>>>(out);

    // 5) PV (writes attn in [T,B,E] layout)
    pv_kernel<<<dim3(T_ / 64, BH_), blk>>>();

    // 6) Output complex linear -> d_out head: out_r then out_i
    cgemm64<<<dim3(E_ / 64, M_ / 64), blk>>>(
        gatr, gati, W_out_r, W_out_i, b_out_r, b_out_i,
        out, out + (size_t)M_ * E_, E_, E_);
}

// round 2
// speedup vs baseline: 3.1178x; 3.1178x over previous
#include <cuda_runtime.h>
#include <cstdint>
#include <cstddef>

// Problem constants
#define T_   1024
#define B_   8
#define E_   512
#define H_   8
#define D_   64
#define BH_  (B_ * H_)          // 64
#define M_   (T_ * B_)          // 8192
#define K3E  (3 * E_)           // 1536
#define SCALE_ 0.125f

#define TT_  (T_ * T_)                       // 1048576
#define OUT_OFF2 (2 * (size_t)T_ * B_ * E_)  // start of aw_avg block in d_out
#define BTT_ ((size_t)B_ * T_ * T_)

// -------------------- scratch (device globals) ------------------------------
__device__ float g_qkv_r[(size_t)M_ * K3E];
__device__ float g_qkv_i[(size_t)M_ * K3E];
__device__ float g_aw_r[(size_t)BH_ * TT_];
__device__ float g_aw_i[(size_t)BH_ * TT_];
__device__ float g_attn_r[(size_t)M_ * E_];
__device__ float g_attn_i[(size_t)M_ * E_];

// -------------------- helpers ------------------------------------------------
__device__ __forceinline__ uint32_t f2tf(float x) {
    uint32_t r;
    asm("cvt.rna.tf32.f32 %0, %1;" : "=r"(r) : "f"(x));
    return r;
}

__device__ __forceinline__ void mma8(float* c, const uint32_t* a, const uint32_t* b) {
    asm volatile(
        "mma.sync.aligned.m16n8k8.row.col.f32.tf32.tf32.f32 "
        "{%0,%1,%2,%3},{%4,%5,%6,%7},{%8,%9},{%0,%1,%2,%3};"
        : "+f"(c[0]), "+f"(c[1]), "+f"(c[2]), "+f"(c[3])
        : "r"(a[0]), "r"(a[1]), "r"(a[2]), "r"(a[3]), "r"(b[0]), "r"(b[1]));
}

__device__ __forceinline__ void cp16(uint32_t s, const float* g) {
    asm volatile("cp.async.cg.shared.global [%0], [%1], 16;"
                 :: "r"(s), "l"((unsigned long long)__cvta_generic_to_global(g)));
}

// ---------------------------------------------------------------------------
// Complex GEMM on tensor cores (tf32).
//   C = (Ar + iAi) @ op(Br + iBi) + bias ; op = conj-transpose-ish per flags.
//   A: [M, K] row-major (lda), logical B: [N, K] (B_KN=false, row-major [n][k])
//   or [K, N] (B_KN=true, row-major [k][n]).
//   CONJ=false: cr = ar*br - ai*bi ; ci = ai*br + ar*bi   (plain complex mul)
//   CONJ=true : cr = ar*br + ai*bi ; ci = ai*br - ar*bi   (B conjugated)
//   Batched via blockIdx.z: zb = z>>3, zh = z&7, base += zb*s1 + zh*s2.
// Block: 256 thr, tile M=128, N=64, KC=32, double-buffered cp.async.
// ---------------------------------------------------------------------------
template <bool CONJ, bool B_KN>
__global__ __launch_bounds__(256, 2)
void cmma_kernel(const float* __restrict__ Ar, const float* __restrict__ Ai,
                 long lda, long sA1, long sA2,
                 const float* __restrict__ Br, const float* __restrict__ Bi,
                 long ldb, long sB1, long sB2,
                 float* __restrict__ Cr, float* __restrict__ Ci,
                 long ldc, long sC1, long sC2,
                 const float* __restrict__ biasr, const float* __restrict__ biasi,
                 float alpha, int K)
{
    extern __shared__ float sm[];
    constexpr int AS = 128 * 36;                 // floats per A buffer per comp
    constexpr int BS = B_KN ? (32 * 68) : (64 * 36);
    float* AsR = sm;                             // [2][AS]
    float* AsI = sm + 2 * AS;
    float* BsR = sm + 4 * AS;                    // [2][BS]
    float* BsI = sm + 4 * AS + 2 * BS;

    const int tid  = threadIdx.x;
    const int lane = tid & 31;
    const int warp = tid >> 5;
    const int wm   = warp & 3;     // M direction (4 warps of 32 rows)
    const int wn   = warp >> 2;    // N direction (2 warps of 32 cols)
    const int grp  = lane >> 2;    // 0..7
    const int quad = lane & 3;     // 0..3

    const int bz = blockIdx.z;
    const int zb = bz >> 3, zh = bz & 7;
    const int m0 = blockIdx.y << 7;
    const int n0 = blockIdx.x << 6;

    const float* ArB = Ar + (size_t)zb * sA1 + (size_t)zh * sA2;
    const float* AiB = Ai + (size_t)zb * sA1 + (size_t)zh * sA2;
    const float* BrB = Br + (size_t)zb * sB1 + (size_t)zh * sB2;
    const float* BiB = Bi + (size_t)zb * sB1 + (size_t)zh * sB2;

    const uint32_t sAsR = (uint32_t)__cvta_generic_to_shared(AsR);
    const uint32_t sAsI = (uint32_t)__cvta_generic_to_shared(AsI);
    const uint32_t sBsR = (uint32_t)__cvta_generic_to_shared(BsR);
    const uint32_t sBsI = (uint32_t)__cvta_generic_to_shared(BsI);

    float cr[2][4][4], ci[2][4][4];
#pragma unroll
    for (int mi = 0; mi < 2; mi++)
#pragma unroll
        for (int ni = 0; ni < 4; ni++)
#pragma unroll
            for (int r = 0; r < 4; r++) { cr[mi][ni][r] = 0.f; ci[mi][ni][r] = 0.f; }

    const int NC = K >> 5;

    auto load_chunk = [&](int c, int buf) {
        const int k0 = c << 5;
        // A tile: 128 rows x 32 floats, 4 float4 per thread per component
#pragma unroll
        for (int j = 0; j < 4; j++) {
            int idx = tid + j * 256;
            int row = idx >> 3;
            int c4  = (idx & 7) << 2;
            uint32_t so = (uint32_t)((buf * AS + row * 36 + c4) * 4);
            cp16(sAsR + so, ArB + (size_t)(m0 + row) * lda + k0 + c4);
            cp16(sAsI + so, AiB + (size_t)(m0 + row) * lda + k0 + c4);
        }
        if (B_KN) {
            // B tile: 32 k-rows x 64 n-cols
#pragma unroll
            for (int j = 0; j < 2; j++) {
                int idx = tid + j * 256;
                int row = idx >> 4;
                int c4  = (idx & 15) << 2;
                uint32_t so = (uint32_t)((buf * BS + row * 68 + c4) * 4);
                cp16(sBsR + so, BrB + (size_t)(k0 + row) * ldb + n0 + c4);
                cp16(sBsI + so, BiB + (size_t)(k0 + row) * ldb + n0 + c4);
            }
        } else {
            // B tile: 64 n-rows x 32 k-cols
#pragma unroll
            for (int j = 0; j < 2; j++) {
                int idx = tid + j * 256;
                int row = idx >> 3;
                int c4  = (idx & 7) << 2;
                uint32_t so = (uint32_t)((buf * BS + row * 36 + c4) * 4);
                cp16(sBsR + so, BrB + (size_t)(n0 + row) * ldb + k0 + c4);
                cp16(sBsI + so, BiB + (size_t)(n0 + row) * ldb + k0 + c4);
            }
        }
    };

    load_chunk(0, 0);
    asm volatile("cp.async.commit_group;");

    for (int c = 0; c < NC; c++) {
        if (c + 1 < NC) load_chunk(c + 1, (c + 1) & 1);
        asm volatile("cp.async.commit_group;");
        asm volatile("cp.async.wait_group 1;");
        __syncthreads();

        const float* aR = AsR + (c & 1) * AS;
        const float* aI = AsI + (c & 1) * AS;
        const float* bR = BsR + (c & 1) * BS;
        const float* bI = BsI + (c & 1) * BS;

#pragma unroll
        for (int ks = 0; ks < 4; ks++) {
            const int kk = ks * 8 + quad;
            uint32_t afr[2][4], afi[2][4];
#pragma unroll
            for (int mi = 0; mi < 2; mi++) {
                int r0 = wm * 32 + mi * 16 + grp;
                afr[mi][0] = f2tf(aR[r0 * 36 + kk]);
                afr[mi][1] = f2tf(aR[(r0 + 8) * 36 + kk]);
                afr[mi][2] = f2tf(aR[r0 * 36 + kk + 4]);
                afr[mi][3] = f2tf(aR[(r0 + 8) * 36 + kk + 4]);
                afi[mi][0] = f2tf(aI[r0 * 36 + kk]);
                afi[mi][1] = f2tf(aI[(r0 + 8) * 36 + kk]);
                afi[mi][2] = f2tf(aI[r0 * 36 + kk + 4]);
                afi[mi][3] = f2tf(aI[(r0 + 8) * 36 + kk + 4]);
            }
#pragma unroll
            for (int ni = 0; ni < 4; ni++) {
                int nn = wn * 32 + ni * 8 + grp;
                uint32_t bfr[2], bfi[2], bfx[2];
                if (B_KN) {
                    bfr[0] = f2tf(bR[kk * 68 + nn]);
                    bfr[1] = f2tf(bR[(kk + 4) * 68 + nn]);
                    bfi[0] = f2tf(bI[kk * 68 + nn]);
                    bfi[1] = f2tf(bI[(kk + 4) * 68 + nn]);
                } else {
                    bfr[0] = f2tf(bR[nn * 36 + kk]);
                    bfr[1] = f2tf(bR[nn * 36 + kk + 4]);
                    bfi[0] = f2tf(bI[nn * 36 + kk]);
                    bfi[1] = f2tf(bI[nn * 36 + kk + 4]);
                }
                bfx[0] = bfi[0] ^ 0x80000000u;
                bfx[1] = bfi[1] ^ 0x80000000u;
#pragma unroll
                for (int mi = 0; mi < 2; mi++) {
                    mma8(cr[mi][ni], afr[mi], bfr);
                    mma8(cr[mi][ni], afi[mi], CONJ ? bfi : bfx);
                    mma8(ci[mi][ni], afi[mi], bfr);
                    mma8(ci[mi][ni], afr[mi], CONJ ? bfx : bfi);
                }
            }
        }
        __syncthreads();
    }

    // Epilogue
    float* CrB = Cr + (size_t)zb * sC1 + (size_t)zh * sC2;
    float* CiB = Ci + (size_t)zb * sC1 + (size_t)zh * sC2;
#pragma unroll
    for (int mi = 0; mi < 2; mi++) {
#pragma unroll
        for (int ni = 0; ni < 4; ni++) {
            int m = m0 + wm * 32 + mi * 16 + grp;
            int n = n0 + wn * 32 + ni * 8 + quad * 2;
            float br0 = 0.f, br1 = 0.f, bi0 = 0.f, bi1 = 0.f;
            if (biasr) {
                br0 = biasr[n]; br1 = biasr[n + 1];
                bi0 = biasi[n]; bi1 = biasi[n + 1];
            }
            float2 v;
            v.x = cr[mi][ni][0] * alpha + br0;
            v.y = cr[mi][ni][1] * alpha + br1;
            *(float2*)(CrB + (size_t)m * ldc + n) = v;
            v.x = cr[mi][ni][2] * alpha + br0;
            v.y = cr[mi][ni][3] * alpha + br1;
            *(float2*)(CrB + (size_t)(m + 8) * ldc + n) = v;
            v.x = ci[mi][ni][0] * alpha + bi0;
            v.y = ci[mi][ni][1] * alpha + bi1;
            *(float2*)(CiB + (size_t)m * ldc + n) = v;
            v.x = ci[mi][ni][2] * alpha + bi0;
            v.y = ci[mi][ni][3] * alpha + bi1;
            *(float2*)(CiB + (size_t)(m + 8) * ldc + n) = v;
        }
    }
}

// ---------------------------------------------------------------------------
// Row softmax in place over g_aw_r / g_aw_i. One block per row.
// ---------------------------------------------------------------------------
__global__ __launch_bounds__(256) void softmax_kernel()
{
    const unsigned rows = BH_ * T_;
    const unsigned x = blockIdx.x;
    float* buf = (x >= rows) ? g_aw_i : g_aw_r;
    const size_t row = (size_t)(x & (rows - 1));
    float* p = buf + row * T_;

    const int tid = threadIdx.x;
    float4 v = *(const float4*)&p[tid << 2];

    __shared__ float red[256];
    float m = fmaxf(fmaxf(v.x, v.y), fmaxf(v.z, v.w));
    red[tid] = m;
    __syncthreads();
#pragma unroll
    for (int off = 128; off > 0; off >>= 1) {
        if (tid < off) red[tid] = fmaxf(red[tid], red[tid + off]);
        __syncthreads();
    }
    const float rmax = red[0];
    __syncthreads();

    float4 e;
    e.x = expf(v.x - rmax);
    e.y = expf(v.y - rmax);
    e.z = expf(v.z - rmax);
    e.w = expf(v.w - rmax);
    red[tid] = e.x + e.y + e.z + e.w;
    __syncthreads();
#pragma unroll
    for (int off = 128; off > 0; off >>= 1) {
        if (tid < off) red[tid] += red[tid + off];
        __syncthreads();
    }
    const float inv = 1.0f / red[0];

    e.x *= inv; e.y *= inv; e.z *= inv; e.w *= inv;
    *(float4*)&p[tid << 2] = e;
}

// ---------------------------------------------------------------------------
// Head-average of attention weights -> d_out tail [2, B, T, T]
// ---------------------------------------------------------------------------
__global__ __launch_bounds__(256) void avg_kernel(float* __restrict__ out)
{
    const int t = blockIdx.x;
    const int b = blockIdx.y;
    const int s = threadIdx.x << 2;

    float4 sr = {0.f, 0.f, 0.f, 0.f};
    float4 si = {0.f, 0.f, 0.f, 0.f};
#pragma unroll
    for (int h = 0; h < H_; h++) {
        size_t base = ((size_t)(b * H_ + h) * T_ + t) * T_ + s;
        float4 r  = *(const float4*)&g_aw_r[base];
        float4 im = *(const float4*)&g_aw_i[base];
        sr.x += r.x;  sr.y += r.y;  sr.z += r.z;  sr.w += r.w;
        si.x += im.x; si.y += im.y; si.z += im.z; si.w += im.w;
    }
    const float inv = 1.0f / (float)H_;
    sr.x *= inv; sr.y *= inv; sr.z *= inv; sr.w *= inv;
    si.x *= inv; si.y *= inv; si.z *= inv; si.w *= inv;

    size_t o = ((size_t)b * T_ + t) * T_ + s;
    *(float4*)&out[OUT_OFF2 + o]        = sr;
    *(float4*)&out[OUT_OFF2 + BTT_ + o] = si;
}

// ---------------------------------------------------------------------------
extern "C" void kernel_launch(void* const* d_in, const int* in_sizes, int n_in,
                              void* d_out, int out_size)
{
    const float* query_r = (const float*)d_in[0];
    const float* query_i = (const float*)d_in[1];
    const float* W_qkv_r = (const float*)d_in[2];
    const float* W_qkv_i = (const float*)d_in[3];
    const float* b_qkv_r = (const float*)d_in[4];
    const float* b_qkv_i = (const float*)d_in[5];
    const float* W_out_r = (const float*)d_in[6];
    const float* W_out_i = (const float*)d_in[7];
    const float* b_out_r = (const float*)d_in[8];
    const float* b_out_i = (const float*)d_in[9];
    float* out = (float*)d_out;

    float *gqkvr, *gqkvi, *gawr, *gawi, *gatr, *gati;
    cudaGetSymbolAddress((void**)&gqkvr, g_qkv_r);
    cudaGetSymbolAddress((void**)&gqkvi, g_qkv_i);
    cudaGetSymbolAddress((void**)&gawr, g_aw_r);
    cudaGetSymbolAddress((void**)&gawi, g_aw_i);
    cudaGetSymbolAddress((void**)&gatr, g_attn_r);
    cudaGetSymbolAddress((void**)&gati, g_attn_i);

    const int SMEM_NK = (4 * 128 * 36 + 4 * 64 * 36) * 4;   // 110592 B
    const int SMEM_KN = (4 * 128 * 36 + 4 * 32 * 68) * 4;   // 108544 B

    cudaFuncSetAttribute((const void*)cmma_kernel<false, false>,
                         cudaFuncAttributeMaxDynamicSharedMemorySize, SMEM_NK);
    cudaFuncSetAttribute((const void*)cmma_kernel<true, false>,
                         cudaFuncAttributeMaxDynamicSharedMemorySize, SMEM_NK);
    cudaFuncSetAttribute((const void*)cmma_kernel<true, true>,
                         cudaFuncAttributeMaxDynamicSharedMemorySize, SMEM_KN);

    dim3 blk(256);

    // 1) QKV complex linear: [8192,512] @ [1536,512]^T -> g_qkv [8192,1536]
    cmma_kernel<false, false><<<dim3(K3E / 64, M_ / 128, 1), blk, SMEM_NK>>>(
        query_r, query_i, E_, 0, 0,
        W_qkv_r, W_qkv_i, E_, 0, 0,
        gqkvr, gqkvi, K3E, 0, 0,
        b_qkv_r, b_qkv_i, 1.0f, E_);

    // 2) Scores: per (b,h): q[1024,64] @ conj(k)[1024,64]^T * SCALE -> aw logits
    cmma_kernel<true, false><<<dim3(T_ / 64, T_ / 128, BH_), blk, SMEM_NK>>>(
        gqkvr, gqkvi, (long)B_ * K3E, K3E, D_,
        gqkvr + E_, gqkvi + E_, (long)B_ * K3E, K3E, D_,
        gawr, gawi, T_, (long)8 * TT_, (long)TT_,
        nullptr, nullptr, SCALE_, D_);

    // 3) Softmax in place (real + imag)
    softmax_kernel<<<dim3(2 * BH_ * T_), blk>>>();

    // 4) Head-averaged attention weights -> d_out tail
    avg_kernel<<<dim3(T_, B_), blk>>>(out);

    // 5) PV: per (b,h): aw[1024,1024] @ conj(v)[1024,64] -> attn in [T,B,E]
    cmma_kernel<true, true><<<dim3(1, T_ / 128, BH_), blk, SMEM_KN>>>(
        gawr, gawi, T_, (long)8 * TT_, (long)TT_,
        gqkvr + 2 * E_, gqkvi + 2 * E_, (long)B_ * K3E, K3E, D_,
        gatr, gati, (long)B_ * E_, E_, D_,
        nullptr, nullptr, 1.0f, T_);

    // 6) Output complex linear -> d_out head (out_r, out_i)
    cmma_kernel<false, false><<<dim3(E_ / 64, M_ / 128, 1), blk, SMEM_NK>>>(
        gatr, gati, E_, 0, 0,
        W_out_r, W_out_i, E_, 0, 0,
        out, out + (size_t)M_ * E_, E_, 0, 0,
        b_out_r, b_out_i, 1.0f, E_);
}